// round 10
// baseline (speedup 1.0000x reference)
#include <cuda_runtime.h>
#include <cuda_bf16.h>
#include <cstdint>

// ============================================================================
// DirectedEdgeEncoder on sm_103 (non-'a' target: mma.sync/ldmatrix only).
//
//   out[e] = relu( xW[row[e]] + edge_attr[e] @ W2^T )
//   xW[n]  = x[n] @ W1^T + b          (phase 0, per node)
//
// GEMMs: [M x 64] @ [64 x 128] via m16n8k16 bf16, 3-term hi/lo split.
// Physical tiles store [hi | lo]; per K-chunk cc:
//   acc += A.hi x B.hi;  acc += A.lo x B.hi;  acc += A.hi x B.lo
//
// Round-8: R7 + cross-tile software pipeline: double-buffered A (+idx),
// convert(t+1) moved after epilogue(t), ONE __syncthreads per iteration.
// ============================================================================

#define M_TILE   256
#define NT       512
#define AROW     256           // bytes per smem row (128 bf16: hi|lo)

// smem layout (bytes)
#define SM_A0    0                     // 256 x 256 = 65536
#define SM_A1    65536                 // 256 x 256 = 65536
#define SM_B     131072                // 128 x 256 = 32768
#define SM_IDX0  163840                // 256 int
#define SM_IDX1  164864                // 256 int
#define SM_FLAG  165888
#define SM_TOTAL (SM_FLAG + 16)        // 165904

__device__ float g_xW[50432 * 128];    // node @ W1^T + b   (25.8 MB)

// ---------------------------------------------------------------------------
__device__ __forceinline__ uint32_t smem_u32(const void* p) {
    uint32_t a;
    asm("{ .reg .u64 t; cvta.to.shared.u64 t, %1; cvt.u32.u64 %0, t; }"
        : "=r"(a) : "l"(p));
    return a;
}

__device__ __forceinline__ void ldmatrix_x4(uint32_t& r0, uint32_t& r1,
                                            uint32_t& r2, uint32_t& r3,
                                            uint32_t addr) {
    asm volatile("ldmatrix.sync.aligned.m8n8.x4.shared.b16 {%0,%1,%2,%3}, [%4];"
                 : "=r"(r0), "=r"(r1), "=r"(r2), "=r"(r3) : "r"(addr));
}

__device__ __forceinline__ void mma_bf16(float* c, const uint32_t* a,
                                         uint32_t b0, uint32_t b1) {
    asm volatile(
        "mma.sync.aligned.m16n8k16.row.col.f32.bf16.bf16.f32 "
        "{%0,%1,%2,%3}, {%4,%5,%6,%7}, {%8,%9}, {%0,%1,%2,%3};"
        : "+f"(c[0]), "+f"(c[1]), "+f"(c[2]), "+f"(c[3])
        : "r"(a[0]), "r"(a[1]), "r"(a[2]), "r"(a[3]), "r"(b0), "r"(b1));
}

__device__ __forceinline__ uint32_t pack_bf2(float a, float b) {
    __nv_bfloat162 t;
    t.x = __float2bfloat16_rn(a);
    t.y = __float2bfloat16_rn(b);
    return *reinterpret_cast<uint32_t*>(&t);
}

__device__ __forceinline__ void split4(float4 v, uint2& hi, uint2& lo) {
    float hx = __bfloat162float(__float2bfloat16_rn(v.x));
    float hy = __bfloat162float(__float2bfloat16_rn(v.y));
    float hz = __bfloat162float(__float2bfloat16_rn(v.z));
    float hw = __bfloat162float(__float2bfloat16_rn(v.w));
    hi.x = pack_bf2(v.x, v.y);
    hi.y = pack_bf2(v.z, v.w);
    lo.x = pack_bf2(v.x - hx, v.y - hy);
    lo.y = pack_bf2(v.z - hz, v.w - hw);
}

// swizzled 8B store: row r, 128B block blk (0/1), 8B slot j (0..15)
__device__ __forceinline__ void sw_store8(char* base, int r, int blk, int j,
                                          uint2 v) {
    uint32_t off = (uint32_t)r * AROW + (uint32_t)blk * 128
                 + ((uint32_t)(((j >> 1) ^ (r & 7))) << 4) + ((j & 1) << 3);
    *(uint2*)(base + off) = v;
}

__device__ __forceinline__ void load_tile(float4* f, const float* __restrict__ src,
                                          int t, int M_total, int tid) {
    #pragma unroll
    for (int i = 0; i < 8; i++) {
        int idx = i * NT + tid;              // 0..4095
        int r = idx >> 4, j = idx & 15;
        int gr = t * M_TILE + r;
        if (gr >= M_total) gr = 0;           // clamp; stores guarded later
        f[i] = __ldg((const float4*)(src + (size_t)gr * 64 + j * 4));
    }
}

__device__ __forceinline__ void convert_tile(char* aBase, const float4* f,
                                             int tid) {
    const int j = tid & 15;
    #pragma unroll
    for (int i = 0; i < 8; i++) {
        int r = i * 32 + (tid >> 4);
        uint2 hi, lo;
        split4(f[i], hi, lo);
        sw_store8(aBase, r, 0, j, hi);
        sw_store8(aBase, r, 1, j, lo);
    }
}

__device__ __forceinline__ void stage_idx(int* idx_s, const void* eidx,
                                          int is64, int t, int M_total,
                                          int tid) {
    if (tid < M_TILE) {
        int e = t * M_TILE + tid;
        int r = 0;
        if (e < M_total)
            r = is64 ? (int)((const long long*)eidx)[e]
                     : ((const int*)eidx)[e];
        idx_s[tid] = r;
    }
}

// ---------------------------------------------------------------------------
// PHASE 0: g_xW[r] = x[r] @ W[:, :64]^T + bias
// PHASE 1: out[e]  = relu( edge_attr[e] @ W[:, 64:]^T + g_xW[row[e]] )
// ---------------------------------------------------------------------------
template <int PHASE>
__global__ void __launch_bounds__(NT, 1)
gemm_kernel(float* __restrict__ out,
            const float* __restrict__ src,        // x or edge_attr [M,64]
            const void*  __restrict__ eidx,
            const float* __restrict__ W,          // [128,128]
            const float* __restrict__ bias,
            int M_total, int n_tiles) {
    extern __shared__ char smem[];
    const int tid  = threadIdx.x;
    const int wid  = tid >> 5;
    const int lane = tid & 31;
    const uint32_t sb = smem_u32(smem);

    // ---- dtype sniff for edge_index (int64 LE: odd 32-bit words all zero)
    if (PHASE == 1 && tid < 32) {
        unsigned v = 0;
        #pragma unroll
        for (int s = 0; s < 4; s++)
            v |= ((const unsigned*)eidx)[1 + 2 * (tid * 4 + s)];
        unsigned any = __ballot_sync(0xffffffffu, v != 0u);
        if (tid == 0) *(int*)(smem + SM_FLAG) = (any == 0u) ? 1 : 0;
    }

    // ---- build column-permuted B tile: physical [hi | lo]
    {
        const float* Wp = W + (PHASE == 0 ? 0 : 64);
        #pragma unroll
        for (int i = 0; i < 4; i++) {
            int idx = i * NT + tid;              // 0..2047
            int ns = idx >> 4;                   // B smem row 0..127
            int j  = idx & 15;
            int nw   = ns >> 6;
            int rest = ns & 63;
            int ni = rest >> 3, pos = rest & 7;
            int q = pos >> 1, jj = pos & 1;
            int L = nw * 64 + ((ni >> 1) << 4) + (q << 2) + ((ni & 1) << 1) + jj;
            float4 v = *(const float4*)(Wp + L * 128 + j * 4);
            uint2 hi, lo;
            split4(v, hi, lo);
            sw_store8(smem + SM_B, ns, 0, j, hi);
            sw_store8(smem + SM_B, ns, 1, j, lo);
        }
    }

    // ---- prologue: load + convert first tile into A0
    float4 f[8];
    if (blockIdx.x < n_tiles) load_tile(f, src, blockIdx.x, M_total, tid);
    __syncthreads();                     // B + flag ready
    const int is64 = (PHASE == 1) ? *(const int*)(smem + SM_FLAG) : 0;
    if (blockIdx.x < n_tiles) {
        convert_tile(smem + SM_A0, f, tid);
        if (PHASE == 1)
            stage_idx((int*)(smem + SM_IDX0), eidx, is64, blockIdx.x,
                      M_total, tid);
    }
    __syncthreads();                     // A0 + idx0 ready

    const int mwarp = wid >> 1;              // 0..7  (32 rows each)
    const int nwarp = wid & 1;               // 0..1  (64 cols each)
    const int q     = lane & 3;

    const int aRow = mwarp * 32 + (lane & 7) + (((lane >> 3) & 1) << 3);
    const uint32_t aRowStride = (uint32_t)aRow * AROW;
    const int aRx = aRow & 7;
    const int aHalf = lane >> 4;
    const int bRowBase = nwarp * 64 + ((lane >> 4) << 3) + (lane & 7);
    const int bHalf = (lane >> 3) & 1;

    float4 bias4[4];
    if (PHASE == 0) {
        #pragma unroll
        for (int p = 0; p < 4; p++)
            bias4[p] = ((const float4*)bias)[nwarp * 16 + p * 4 + q];
    }

    int cur = 0;
    for (int t = blockIdx.x; t < n_tiles; t += gridDim.x) {
        const uint32_t aBase = sb + (cur ? SM_A1 : SM_A0);
        const uint32_t aRowOff = aBase + aRowStride;
        int* idx_s = (int*)(smem + (cur ? SM_IDX1 : SM_IDX0));

        // ---- MMA: warp tile M32 x N64; cc-outer, fragments loaded once
        float acc[2][8][4];
        #pragma unroll
        for (int mi = 0; mi < 2; mi++)
            #pragma unroll
            for (int ni = 0; ni < 8; ni++)
                #pragma unroll
                for (int c = 0; c < 4; c++) acc[mi][ni][c] = 0.0f;

        #pragma unroll
        for (int cc = 0; cc < 4; cc++) {
            const int cbase = cc * 2;
            uint32_t ah[2][4], al[2][4];
            #pragma unroll
            for (int mi = 0; mi < 2; mi++) {
                uint32_t base = aRowOff + (uint32_t)mi * 16 * AROW
                    + ((uint32_t)((cbase + aHalf) ^ aRx) << 4);
                ldmatrix_x4(ah[mi][0], ah[mi][1], ah[mi][2], ah[mi][3], base);
                ldmatrix_x4(al[mi][0], al[mi][1], al[mi][2], al[mi][3],
                            base + 128);
            }
            uint32_t b[8][2];
            #pragma unroll
            for (int p = 0; p < 4; p++) {
                int brow = bRowBase + p * 16;
                uint32_t addr = sb + SM_B + (uint32_t)brow * AROW
                    + ((uint32_t)((cbase + bHalf) ^ (brow & 7)) << 4);
                ldmatrix_x4(b[2*p][0], b[2*p][1], b[2*p+1][0], b[2*p+1][1],
                            addr);
            }
            #pragma unroll
            for (int mi = 0; mi < 2; mi++)
                #pragma unroll
                for (int ni = 0; ni < 8; ni++)
                    mma_bf16(acc[mi][ni], ah[mi], b[ni][0], b[ni][1]);
            #pragma unroll
            for (int mi = 0; mi < 2; mi++)
                #pragma unroll
                for (int ni = 0; ni < 8; ni++)
                    mma_bf16(acc[mi][ni], al[mi], b[ni][0], b[ni][1]);
            #pragma unroll
            for (int p = 0; p < 4; p++) {
                int brow = bRowBase + p * 16;
                uint32_t addr = sb + SM_B + (uint32_t)brow * AROW + 128
                    + ((uint32_t)((cbase + bHalf) ^ (brow & 7)) << 4);
                ldmatrix_x4(b[2*p][0], b[2*p][1], b[2*p+1][0], b[2*p+1][1],
                            addr);
            }
            #pragma unroll
            for (int mi = 0; mi < 2; mi++)
                #pragma unroll
                for (int ni = 0; ni < 8; ni++)
                    mma_bf16(acc[mi][ni], ah[mi], b[ni][0], b[ni][1]);
        }

        // ---- prefetch next tile (LDG hidden under epilogue)
        const int tn = t + gridDim.x;
        if (tn < n_tiles) load_tile(f, src, tn, M_total, tid);

        // ---- epilogue: float4 fragments at logical cols nwarp*64+16p+4q
        const int colF4 = nwarp * 16 + q;
        #pragma unroll
        for (int mi = 0; mi < 2; mi++) {
            int r0 = mwarp * 32 + mi * 16 + (lane >> 2);
            int r1 = r0 + 8;
            if (PHASE == 1) {
                const float4* xp0 = (const float4*)
                    (g_xW + (size_t)idx_s[r0] * 128) + colF4;
                const float4* xp1 = (const float4*)
                    (g_xW + (size_t)idx_s[r1] * 128) + colF4;
                float4 g0[4], g1[4];
                #pragma unroll
                for (int p = 0; p < 4; p++) { g0[p] = __ldg(xp0 + p * 4);
                                              g1[p] = __ldg(xp1 + p * 4); }
                int rg0 = t * M_TILE + r0, rg1 = t * M_TILE + r1;
                float4* op0 = (float4*)out + (size_t)rg0 * 32 + colF4;
                float4* op1 = (float4*)out + (size_t)rg1 * 32 + colF4;
                #pragma unroll
                for (int p = 0; p < 4; p++) {
                    float4 o;
                    o.x = fmaxf(acc[mi][2*p][0]   + g0[p].x, 0.0f);
                    o.y = fmaxf(acc[mi][2*p][1]   + g0[p].y, 0.0f);
                    o.z = fmaxf(acc[mi][2*p+1][0] + g0[p].z, 0.0f);
                    o.w = fmaxf(acc[mi][2*p+1][1] + g0[p].w, 0.0f);
                    if (rg0 < M_total) op0[p * 4] = o;
                    o.x = fmaxf(acc[mi][2*p][2]   + g1[p].x, 0.0f);
                    o.y = fmaxf(acc[mi][2*p][3]   + g1[p].y, 0.0f);
                    o.z = fmaxf(acc[mi][2*p+1][2] + g1[p].z, 0.0f);
                    o.w = fmaxf(acc[mi][2*p+1][3] + g1[p].w, 0.0f);
                    if (rg1 < M_total) op1[p * 4] = o;
                }
            } else {
                int rg0 = t * M_TILE + r0, rg1 = t * M_TILE + r1;
                float4* op0 = (float4*)g_xW + (size_t)rg0 * 32 + colF4;
                float4* op1 = (float4*)g_xW + (size_t)rg1 * 32 + colF4;
                #pragma unroll
                for (int p = 0; p < 4; p++) {
                    float4 o;
                    o.x = acc[mi][2*p][0]   + bias4[p].x;
                    o.y = acc[mi][2*p][1]   + bias4[p].y;
                    o.z = acc[mi][2*p+1][0] + bias4[p].z;
                    o.w = acc[mi][2*p+1][1] + bias4[p].w;
                    if (rg0 < M_total) op0[p * 4] = o;
                    o.x = acc[mi][2*p][2]   + bias4[p].x;
                    o.y = acc[mi][2*p][3]   + bias4[p].y;
                    o.z = acc[mi][2*p+1][2] + bias4[p].z;
                    o.w = acc[mi][2*p+1][3] + bias4[p].w;
                    if (rg1 < M_total) op1[p * 4] = o;
                }
            }
        }

        // ---- convert next tile into the other A buffer (safe: A[nxt] was
        //      last read by MMA(t-1), fenced by the previous iteration sync)
        if (tn < n_tiles) {
            convert_tile(smem + (cur ? SM_A0 : SM_A1), f, tid);
            if (PHASE == 1)
                stage_idx((int*)(smem + (cur ? SM_IDX0 : SM_IDX1)),
                          eidx, is64, tn, M_total, tid);
        }
        __syncthreads();                 // single sync per iteration
        cur ^= 1;
    }
}

// ---------------------------------------------------------------------------
extern "C" void kernel_launch(void* const* d_in, const int* in_sizes, int n_in,
                              void* d_out, int out_size) {
    const float* x         = (const float*)d_in[0];
    const float* edge_attr = (const float*)d_in[1];
    const void*  eidx      = d_in[2];
    const float* W         = (const float*)d_in[3];
    const float* bias      = (const float*)d_in[4];
    float* out             = (float*)d_out;

    const int Nn = in_sizes[0] / 64;
    const int E  = in_sizes[1] / 64;
    const int tiles0 = (Nn + M_TILE - 1) / M_TILE;
    const int tiles1 = (E  + M_TILE - 1) / M_TILE;

    cudaFuncSetAttribute(gemm_kernel<0>,
                         cudaFuncAttributeMaxDynamicSharedMemorySize, SM_TOTAL);
    cudaFuncSetAttribute(gemm_kernel<1>,
                         cudaFuncAttributeMaxDynamicSharedMemorySize, SM_TOTAL);

    int grid0 = tiles0 < 152 ? tiles0 : 152;
    gemm_kernel<0><<<grid0, NT, SM_TOTAL>>>(nullptr, x, eidx, W, bias,
                                            Nn, tiles0);
    int grid1 = tiles1 < 152 ? tiles1 : 152;
    gemm_kernel<1><<<grid1, NT, SM_TOTAL>>>(out, edge_attr, eidx, W, bias,
                                            E, tiles1);
}

// round 11
// speedup vs baseline: 1.0012x; 1.0012x over previous
#include <cuda_runtime.h>
#include <cuda_bf16.h>
#include <cstdint>

// ============================================================================
// DirectedEdgeEncoder on sm_103 (non-'a' target: mma.sync/ldmatrix only).
//
//   out[e] = relu( xW[row[e]] + edge_attr[e] @ W2^T )
//   xW[n]  = x[n] @ W1^T + b          (phase 0, per node)
//
// GEMMs: [M x 64] @ [64 x 128] via m16n8k16 bf16, 3-term hi/lo split.
// Physical tiles store [hi | lo]; per K-chunk cc:
//   acc += A.hi x B.hi;  acc += A.lo x B.hi;  acc += A.hi x B.lo
//
// Round-8: R7 + cross-tile software pipeline: double-buffered A (+idx),
// convert(t+1) moved after epilogue(t), ONE __syncthreads per iteration.
// ============================================================================

#define M_TILE   256
#define NT       512
#define AROW     256           // bytes per smem row (128 bf16: hi|lo)

// smem layout (bytes)
#define SM_A0    0                     // 256 x 256 = 65536
#define SM_A1    65536                 // 256 x 256 = 65536
#define SM_B     131072                // 128 x 256 = 32768
#define SM_IDX0  163840                // 256 int
#define SM_IDX1  164864                // 256 int
#define SM_FLAG  165888
#define SM_TOTAL (SM_FLAG + 16)        // 165904

__device__ float g_xW[50432 * 128];    // node @ W1^T + b   (25.8 MB)

// ---------------------------------------------------------------------------
__device__ __forceinline__ uint32_t smem_u32(const void* p) {
    uint32_t a;
    asm("{ .reg .u64 t; cvta.to.shared.u64 t, %1; cvt.u32.u64 %0, t; }"
        : "=r"(a) : "l"(p));
    return a;
}

__device__ __forceinline__ void ldmatrix_x4(uint32_t& r0, uint32_t& r1,
                                            uint32_t& r2, uint32_t& r3,
                                            uint32_t addr) {
    asm volatile("ldmatrix.sync.aligned.m8n8.x4.shared.b16 {%0,%1,%2,%3}, [%4];"
                 : "=r"(r0), "=r"(r1), "=r"(r2), "=r"(r3) : "r"(addr));
}

__device__ __forceinline__ void mma_bf16(float* c, const uint32_t* a,
                                         uint32_t b0, uint32_t b1) {
    asm volatile(
        "mma.sync.aligned.m16n8k16.row.col.f32.bf16.bf16.f32 "
        "{%0,%1,%2,%3}, {%4,%5,%6,%7}, {%8,%9}, {%0,%1,%2,%3};"
        : "+f"(c[0]), "+f"(c[1]), "+f"(c[2]), "+f"(c[3])
        : "r"(a[0]), "r"(a[1]), "r"(a[2]), "r"(a[3]), "r"(b0), "r"(b1));
}

__device__ __forceinline__ uint32_t pack_bf2(float a, float b) {
    __nv_bfloat162 t;
    t.x = __float2bfloat16_rn(a);
    t.y = __float2bfloat16_rn(b);
    return *reinterpret_cast<uint32_t*>(&t);
}

__device__ __forceinline__ void split4(float4 v, uint2& hi, uint2& lo) {
    float hx = __bfloat162float(__float2bfloat16_rn(v.x));
    float hy = __bfloat162float(__float2bfloat16_rn(v.y));
    float hz = __bfloat162float(__float2bfloat16_rn(v.z));
    float hw = __bfloat162float(__float2bfloat16_rn(v.w));
    hi.x = pack_bf2(v.x, v.y);
    hi.y = pack_bf2(v.z, v.w);
    lo.x = pack_bf2(v.x - hx, v.y - hy);
    lo.y = pack_bf2(v.z - hz, v.w - hw);
}

// swizzled 8B store: row r, 128B block blk (0/1), 8B slot j (0..15)
__device__ __forceinline__ void sw_store8(char* base, int r, int blk, int j,
                                          uint2 v) {
    uint32_t off = (uint32_t)r * AROW + (uint32_t)blk * 128
                 + ((uint32_t)(((j >> 1) ^ (r & 7))) << 4) + ((j & 1) << 3);
    *(uint2*)(base + off) = v;
}

__device__ __forceinline__ void load_tile(float4* f, const float* __restrict__ src,
                                          int t, int M_total, int tid) {
    #pragma unroll
    for (int i = 0; i < 8; i++) {
        int idx = i * NT + tid;              // 0..4095
        int r = idx >> 4, j = idx & 15;
        int gr = t * M_TILE + r;
        if (gr >= M_total) gr = 0;           // clamp; stores guarded later
        f[i] = __ldg((const float4*)(src + (size_t)gr * 64 + j * 4));
    }
}

__device__ __forceinline__ void convert_tile(char* aBase, const float4* f,
                                             int tid) {
    const int j = tid & 15;
    #pragma unroll
    for (int i = 0; i < 8; i++) {
        int r = i * 32 + (tid >> 4);
        uint2 hi, lo;
        split4(f[i], hi, lo);
        sw_store8(aBase, r, 0, j, hi);
        sw_store8(aBase, r, 1, j, lo);
    }
}

__device__ __forceinline__ void stage_idx(int* idx_s, const void* eidx,
                                          int is64, int t, int M_total,
                                          int tid) {
    if (tid < M_TILE) {
        int e = t * M_TILE + tid;
        int r = 0;
        if (e < M_total)
            r = is64 ? (int)((const long long*)eidx)[e]
                     : ((const int*)eidx)[e];
        idx_s[tid] = r;
    }
}

// ---------------------------------------------------------------------------
// PHASE 0: g_xW[r] = x[r] @ W[:, :64]^T + bias
// PHASE 1: out[e]  = relu( edge_attr[e] @ W[:, 64:]^T + g_xW[row[e]] )
// ---------------------------------------------------------------------------
template <int PHASE>
__global__ void __launch_bounds__(NT, 1)
gemm_kernel(float* __restrict__ out,
            const float* __restrict__ src,        // x or edge_attr [M,64]
            const void*  __restrict__ eidx,
            const float* __restrict__ W,          // [128,128]
            const float* __restrict__ bias,
            int M_total, int n_tiles) {
    extern __shared__ char smem[];
    const int tid  = threadIdx.x;
    const int wid  = tid >> 5;
    const int lane = tid & 31;
    const uint32_t sb = smem_u32(smem);

    // ---- dtype sniff for edge_index (int64 LE: odd 32-bit words all zero)
    if (PHASE == 1 && tid < 32) {
        unsigned v = 0;
        #pragma unroll
        for (int s = 0; s < 4; s++)
            v |= ((const unsigned*)eidx)[1 + 2 * (tid * 4 + s)];
        unsigned any = __ballot_sync(0xffffffffu, v != 0u);
        if (tid == 0) *(int*)(smem + SM_FLAG) = (any == 0u) ? 1 : 0;
    }

    // ---- build column-permuted B tile: physical [hi | lo]
    {
        const float* Wp = W + (PHASE == 0 ? 0 : 64);
        #pragma unroll
        for (int i = 0; i < 4; i++) {
            int idx = i * NT + tid;              // 0..2047
            int ns = idx >> 4;                   // B smem row 0..127
            int j  = idx & 15;
            int nw   = ns >> 6;
            int rest = ns & 63;
            int ni = rest >> 3, pos = rest & 7;
            int q = pos >> 1, jj = pos & 1;
            int L = nw * 64 + ((ni >> 1) << 4) + (q << 2) + ((ni & 1) << 1) + jj;
            float4 v = *(const float4*)(Wp + L * 128 + j * 4);
            uint2 hi, lo;
            split4(v, hi, lo);
            sw_store8(smem + SM_B, ns, 0, j, hi);
            sw_store8(smem + SM_B, ns, 1, j, lo);
        }
    }

    // ---- prologue: load + convert first tile into A0
    float4 f[8];
    if (blockIdx.x < n_tiles) load_tile(f, src, blockIdx.x, M_total, tid);
    __syncthreads();                     // B + flag ready
    const int is64 = (PHASE == 1) ? *(const int*)(smem + SM_FLAG) : 0;
    if (blockIdx.x < n_tiles) {
        convert_tile(smem + SM_A0, f, tid);
        if (PHASE == 1)
            stage_idx((int*)(smem + SM_IDX0), eidx, is64, blockIdx.x,
                      M_total, tid);
    }
    __syncthreads();                     // A0 + idx0 ready

    const int mwarp = wid >> 1;              // 0..7  (32 rows each)
    const int nwarp = wid & 1;               // 0..1  (64 cols each)
    const int q     = lane & 3;

    const int aRow = mwarp * 32 + (lane & 7) + (((lane >> 3) & 1) << 3);
    const uint32_t aRowStride = (uint32_t)aRow * AROW;
    const int aRx = aRow & 7;
    const int aHalf = lane >> 4;
    const int bRowBase = nwarp * 64 + ((lane >> 4) << 3) + (lane & 7);
    const int bHalf = (lane >> 3) & 1;

    float4 bias4[4];
    if (PHASE == 0) {
        #pragma unroll
        for (int p = 0; p < 4; p++)
            bias4[p] = ((const float4*)bias)[nwarp * 16 + p * 4 + q];
    }

    int cur = 0;
    for (int t = blockIdx.x; t < n_tiles; t += gridDim.x) {
        const uint32_t aBase = sb + (cur ? SM_A1 : SM_A0);
        const uint32_t aRowOff = aBase + aRowStride;
        int* idx_s = (int*)(smem + (cur ? SM_IDX1 : SM_IDX0));

        // ---- MMA: warp tile M32 x N64; cc-outer, fragments loaded once
        float acc[2][8][4];
        #pragma unroll
        for (int mi = 0; mi < 2; mi++)
            #pragma unroll
            for (int ni = 0; ni < 8; ni++)
                #pragma unroll
                for (int c = 0; c < 4; c++) acc[mi][ni][c] = 0.0f;

        #pragma unroll
        for (int cc = 0; cc < 4; cc++) {
            const int cbase = cc * 2;
            uint32_t ah[2][4], al[2][4];
            #pragma unroll
            for (int mi = 0; mi < 2; mi++) {
                uint32_t base = aRowOff + (uint32_t)mi * 16 * AROW
                    + ((uint32_t)((cbase + aHalf) ^ aRx) << 4);
                ldmatrix_x4(ah[mi][0], ah[mi][1], ah[mi][2], ah[mi][3], base);
                ldmatrix_x4(al[mi][0], al[mi][1], al[mi][2], al[mi][3],
                            base + 128);
            }
            uint32_t b[8][2];
            #pragma unroll
            for (int p = 0; p < 4; p++) {
                int brow = bRowBase + p * 16;
                uint32_t addr = sb + SM_B + (uint32_t)brow * AROW
                    + ((uint32_t)((cbase + bHalf) ^ (brow & 7)) << 4);
                ldmatrix_x4(b[2*p][0], b[2*p][1], b[2*p+1][0], b[2*p+1][1],
                            addr);
            }
            #pragma unroll
            for (int mi = 0; mi < 2; mi++)
                #pragma unroll
                for (int ni = 0; ni < 8; ni++)
                    mma_bf16(acc[mi][ni], ah[mi], b[ni][0], b[ni][1]);
            #pragma unroll
            for (int mi = 0; mi < 2; mi++)
                #pragma unroll
                for (int ni = 0; ni < 8; ni++)
                    mma_bf16(acc[mi][ni], al[mi], b[ni][0], b[ni][1]);
            #pragma unroll
            for (int p = 0; p < 4; p++) {
                int brow = bRowBase + p * 16;
                uint32_t addr = sb + SM_B + (uint32_t)brow * AROW + 128
                    + ((uint32_t)((cbase + bHalf) ^ (brow & 7)) << 4);
                ldmatrix_x4(b[2*p][0], b[2*p][1], b[2*p+1][0], b[2*p+1][1],
                            addr);
            }
            #pragma unroll
            for (int mi = 0; mi < 2; mi++)
                #pragma unroll
                for (int ni = 0; ni < 8; ni++)
                    mma_bf16(acc[mi][ni], ah[mi], b[ni][0], b[ni][1]);
        }

        // ---- prefetch next tile (LDG hidden under epilogue)
        const int tn = t + gridDim.x;
        if (tn < n_tiles) load_tile(f, src, tn, M_total, tid);

        // ---- epilogue: float4 fragments at logical cols nwarp*64+16p+4q
        const int colF4 = nwarp * 16 + q;
        #pragma unroll
        for (int mi = 0; mi < 2; mi++) {
            int r0 = mwarp * 32 + mi * 16 + (lane >> 2);
            int r1 = r0 + 8;
            if (PHASE == 1) {
                const float4* xp0 = (const float4*)
                    (g_xW + (size_t)idx_s[r0] * 128) + colF4;
                const float4* xp1 = (const float4*)
                    (g_xW + (size_t)idx_s[r1] * 128) + colF4;
                float4 g0[4], g1[4];
                #pragma unroll
                for (int p = 0; p < 4; p++) { g0[p] = __ldg(xp0 + p * 4);
                                              g1[p] = __ldg(xp1 + p * 4); }
                int rg0 = t * M_TILE + r0, rg1 = t * M_TILE + r1;
                float4* op0 = (float4*)out + (size_t)rg0 * 32 + colF4;
                float4* op1 = (float4*)out + (size_t)rg1 * 32 + colF4;
                #pragma unroll
                for (int p = 0; p < 4; p++) {
                    float4 o;
                    o.x = fmaxf(acc[mi][2*p][0]   + g0[p].x, 0.0f);
                    o.y = fmaxf(acc[mi][2*p][1]   + g0[p].y, 0.0f);
                    o.z = fmaxf(acc[mi][2*p+1][0] + g0[p].z, 0.0f);
                    o.w = fmaxf(acc[mi][2*p+1][1] + g0[p].w, 0.0f);
                    if (rg0 < M_total) op0[p * 4] = o;
                    o.x = fmaxf(acc[mi][2*p][2]   + g1[p].x, 0.0f);
                    o.y = fmaxf(acc[mi][2*p][3]   + g1[p].y, 0.0f);
                    o.z = fmaxf(acc[mi][2*p+1][2] + g1[p].z, 0.0f);
                    o.w = fmaxf(acc[mi][2*p+1][3] + g1[p].w, 0.0f);
                    if (rg1 < M_total) op1[p * 4] = o;
                }
            } else {
                int rg0 = t * M_TILE + r0, rg1 = t * M_TILE + r1;
                float4* op0 = (float4*)g_xW + (size_t)rg0 * 32 + colF4;
                float4* op1 = (float4*)g_xW + (size_t)rg1 * 32 + colF4;
                #pragma unroll
                for (int p = 0; p < 4; p++) {
                    float4 o;
                    o.x = acc[mi][2*p][0]   + bias4[p].x;
                    o.y = acc[mi][2*p][1]   + bias4[p].y;
                    o.z = acc[mi][2*p+1][0] + bias4[p].z;
                    o.w = acc[mi][2*p+1][1] + bias4[p].w;
                    if (rg0 < M_total) op0[p * 4] = o;
                    o.x = acc[mi][2*p][2]   + bias4[p].x;
                    o.y = acc[mi][2*p][3]   + bias4[p].y;
                    o.z = acc[mi][2*p+1][2] + bias4[p].z;
                    o.w = acc[mi][2*p+1][3] + bias4[p].w;
                    if (rg1 < M_total) op1[p * 4] = o;
                }
            }
        }

        // ---- convert next tile into the other A buffer (safe: A[nxt] was
        //      last read by MMA(t-1), fenced by the previous iteration sync)
        if (tn < n_tiles) {
            convert_tile(smem + (cur ? SM_A0 : SM_A1), f, tid);
            if (PHASE == 1)
                stage_idx((int*)(smem + (cur ? SM_IDX0 : SM_IDX1)),
                          eidx, is64, tn, M_total, tid);
        }
        __syncthreads();                 // single sync per iteration
        cur ^= 1;
    }
}

// ---------------------------------------------------------------------------
extern "C" void kernel_launch(void* const* d_in, const int* in_sizes, int n_in,
                              void* d_out, int out_size) {
    const float* x         = (const float*)d_in[0];
    const float* edge_attr = (const float*)d_in[1];
    const void*  eidx      = d_in[2];
    const float* W         = (const float*)d_in[3];
    const float* bias      = (const float*)d_in[4];
    float* out             = (float*)d_out;

    const int Nn = in_sizes[0] / 64;
    const int E  = in_sizes[1] / 64;
    const int tiles0 = (Nn + M_TILE - 1) / M_TILE;
    const int tiles1 = (E  + M_TILE - 1) / M_TILE;

    cudaFuncSetAttribute(gemm_kernel<0>,
                         cudaFuncAttributeMaxDynamicSharedMemorySize, SM_TOTAL);
    cudaFuncSetAttribute(gemm_kernel<1>,
                         cudaFuncAttributeMaxDynamicSharedMemorySize, SM_TOTAL);

    int grid0 = tiles0 < 152 ? tiles0 : 152;
    gemm_kernel<0><<<grid0, NT, SM_TOTAL>>>(nullptr, x, eidx, W, bias,
                                            Nn, tiles0);
    int grid1 = tiles1 < 152 ? tiles1 : 152;
    gemm_kernel<1><<<grid1, NT, SM_TOTAL>>>(out, edge_attr, eidx, W, bias,
                                            E, tiles1);
}

// round 12
// speedup vs baseline: 1.2245x; 1.2231x over previous
#include <cuda_runtime.h>
#include <cuda_fp16.h>
#include <cstdint>

// ============================================================================
// DirectedEdgeEncoder on sm_103 (non-'a' target: mma.sync/ldmatrix only).
//
//   out[e] = relu( xW[row[e]] + edge_attr[e] @ W2^T )
//   xW[n]  = x[n] @ W1^T + b          (phase 0, per node)
//
// GEMMs: [M x 64] @ [64 x 128] via m16n8k16 **fp16**, 2-term hi/lo split:
//   A = [a_hi | a_lo] (fp16),  B = b_hi (fp16)
//   acc += A.hi x B.hi;  acc += A.lo x B.hi     ( = a * fp16(b) )
// Dropped term a*b_lo ~ 2^-12/product -> norm rel_err ~1.4e-4 << 1e-3.
//
// Round-9: R7 lockstep skeleton unchanged; -33% MMA, -33% ldmatrix, B smem
// halved via the fp16 2-term split.
// ============================================================================

#define M_TILE   256
#define NT       512
#define AROW     256           // A smem row: 128 fp16 [hi | lo]
#define BROW     128           // B smem row: 64 fp16 (hi only)

// smem layout (bytes)
#define SM_A     0                     // 256 x 256 = 65536
#define SM_B     65536                 // 128 x 128 = 16384
#define SM_IDX   (65536 + 16384)       // 256 int   = 1024
#define SM_FLAG  (SM_IDX + 1024)
#define SM_TOTAL (SM_FLAG + 16)        // 82960

__device__ float g_xW[50432 * 128];    // node @ W1^T + b   (25.8 MB)

// ---------------------------------------------------------------------------
__device__ __forceinline__ uint32_t smem_u32(const void* p) {
    uint32_t a;
    asm("{ .reg .u64 t; cvta.to.shared.u64 t, %1; cvt.u32.u64 %0, t; }"
        : "=r"(a) : "l"(p));
    return a;
}

__device__ __forceinline__ void ldmatrix_x4(uint32_t& r0, uint32_t& r1,
                                            uint32_t& r2, uint32_t& r3,
                                            uint32_t addr) {
    asm volatile("ldmatrix.sync.aligned.m8n8.x4.shared.b16 {%0,%1,%2,%3}, [%4];"
                 : "=r"(r0), "=r"(r1), "=r"(r2), "=r"(r3) : "r"(addr));
}

__device__ __forceinline__ void mma_f16(float* c, const uint32_t* a,
                                        uint32_t b0, uint32_t b1) {
    asm volatile(
        "mma.sync.aligned.m16n8k16.row.col.f32.f16.f16.f32 "
        "{%0,%1,%2,%3}, {%4,%5,%6,%7}, {%8,%9}, {%0,%1,%2,%3};"
        : "+f"(c[0]), "+f"(c[1]), "+f"(c[2]), "+f"(c[3])
        : "r"(a[0]), "r"(a[1]), "r"(a[2]), "r"(a[3]), "r"(b0), "r"(b1));
}

// float4 -> hi (4 fp16) and lo (4 fp16 residuals)
__device__ __forceinline__ void split4h(float4 v, uint2& hi, uint2& lo) {
    __half2 h0 = __floats2half2_rn(v.x, v.y);
    __half2 h1 = __floats2half2_rn(v.z, v.w);
    float2 f0 = __half22float2(h0);
    float2 f1 = __half22float2(h1);
    __half2 l0 = __floats2half2_rn(v.x - f0.x, v.y - f0.y);
    __half2 l1 = __floats2half2_rn(v.z - f1.x, v.w - f1.y);
    hi.x = *reinterpret_cast<uint32_t*>(&h0);
    hi.y = *reinterpret_cast<uint32_t*>(&h1);
    lo.x = *reinterpret_cast<uint32_t*>(&l0);
    lo.y = *reinterpret_cast<uint32_t*>(&l1);
}

// swizzled 8B store into a tile with row stride `stride`, 128B block blk
__device__ __forceinline__ void sw_store8(char* base, int r, int blk, int j,
                                          uint2 v, int stride) {
    uint32_t off = (uint32_t)r * stride + (uint32_t)blk * 128
                 + ((uint32_t)(((j >> 1) ^ (r & 7))) << 4) + ((j & 1) << 3);
    *(uint2*)(base + off) = v;
}

__device__ __forceinline__ void load_tile(float4* f, const float* __restrict__ src,
                                          int t, int M_total, int tid) {
    #pragma unroll
    for (int i = 0; i < 8; i++) {
        int idx = i * NT + tid;              // 0..4095
        int r = idx >> 4, j = idx & 15;
        int gr = t * M_TILE + r;
        if (gr >= M_total) gr = 0;           // clamp; stores guarded later
        f[i] = __ldg((const float4*)(src + (size_t)gr * 64 + j * 4));
    }
}

// ---------------------------------------------------------------------------
// PHASE 0: g_xW[r] = x[r] @ W[:, :64]^T + bias
// PHASE 1: out[e]  = relu( edge_attr[e] @ W[:, 64:]^T + g_xW[row[e]] )
// ---------------------------------------------------------------------------
template <int PHASE>
__global__ void __launch_bounds__(NT, 1)
gemm_kernel(float* __restrict__ out,
            const float* __restrict__ src,        // x or edge_attr [M,64]
            const void*  __restrict__ eidx,
            const float* __restrict__ W,          // [128,128]
            const float* __restrict__ bias,
            int M_total, int n_tiles) {
    extern __shared__ char smem[];
    const int tid  = threadIdx.x;
    const int wid  = tid >> 5;
    const int lane = tid & 31;
    const uint32_t sb = smem_u32(smem);

    // ---- dtype sniff for edge_index (int64 LE: odd 32-bit words all zero)
    if (PHASE == 1 && tid < 32) {
        unsigned v = 0;
        #pragma unroll
        for (int s = 0; s < 4; s++)
            v |= ((const unsigned*)eidx)[1 + 2 * (tid * 4 + s)];
        unsigned any = __ballot_sync(0xffffffffu, v != 0u);
        if (tid == 0) *(int*)(smem + SM_FLAG) = (any == 0u) ? 1 : 0;
    }

    // ---- build column-permuted B tile: fp16 hi only, 128B rows
    {
        const float* Wp = W + (PHASE == 0 ? 0 : 64);
        #pragma unroll
        for (int i = 0; i < 4; i++) {
            int idx = i * NT + tid;              // 0..2047
            int ns = idx >> 4;                   // B smem row 0..127
            int j  = idx & 15;
            int nw   = ns >> 6;
            int rest = ns & 63;
            int ni = rest >> 3, pos = rest & 7;
            int q = pos >> 1, jj = pos & 1;
            int L = nw * 64 + ((ni >> 1) << 4) + (q << 2) + ((ni & 1) << 1) + jj;
            float4 v = *(const float4*)(Wp + L * 128 + j * 4);
            uint2 hi, lo;
            split4h(v, hi, lo);
            sw_store8(smem + SM_B, ns, 0, j, hi, BROW);
        }
    }

    // ---- prologue: load first tile into registers
    float4 f[8];
    if (blockIdx.x < n_tiles) load_tile(f, src, blockIdx.x, M_total, tid);
    __syncthreads();

    const int is64 = (PHASE == 1) ? *(const int*)(smem + SM_FLAG) : 0;

    const int mwarp = wid >> 1;              // 0..7  (32 rows each)
    const int nwarp = wid & 1;               // 0..1  (64 cols each)
    const int q     = lane & 3;

    const int aRow = mwarp * 32 + (lane & 7) + (((lane >> 3) & 1) << 3);
    const uint32_t aRowOff = sb + SM_A + (uint32_t)aRow * AROW;
    const int aRx = aRow & 7;
    const int aHalf = lane >> 4;
    const int bRowBase = nwarp * 64 + ((lane >> 4) << 3) + (lane & 7);
    const int bHalf = (lane >> 3) & 1;

    float4 bias4[4];
    if (PHASE == 0) {
        #pragma unroll
        for (int p = 0; p < 4; p++)
            bias4[p] = ((const float4*)bias)[nwarp * 16 + p * 4 + q];
    }

    int* idx_s = (int*)(smem + SM_IDX);

    for (int t = blockIdx.x; t < n_tiles; t += gridDim.x) {
        // ---- convert regs -> A tile: fp16 [hi | lo]
        {
            const int j = tid & 15;
            #pragma unroll
            for (int i = 0; i < 8; i++) {
                int r = i * 32 + (tid >> 4);
                uint2 hi, lo;
                split4h(f[i], hi, lo);
                sw_store8(smem + SM_A, r, 0, j, hi, AROW);
                sw_store8(smem + SM_A, r, 1, j, lo, AROW);
            }
        }
        if (PHASE == 1 && tid < M_TILE) {
            int e = t * M_TILE + tid;
            int r = 0;
            if (e < M_total)
                r = is64 ? (int)((const long long*)eidx)[e]
                         : ((const int*)eidx)[e];
            idx_s[tid] = r;
        }
        __syncthreads();

        // ---- MMA: warp tile M32 x N64; per K-chunk: ah x b, al x b
        float acc[2][8][4];
        #pragma unroll
        for (int mi = 0; mi < 2; mi++)
            #pragma unroll
            for (int ni = 0; ni < 8; ni++)
                #pragma unroll
                for (int c = 0; c < 4; c++) acc[mi][ni][c] = 0.0f;

        #pragma unroll
        for (int cc = 0; cc < 4; cc++) {
            const int cbase = cc * 2;
            uint32_t ah[2][4], al[2][4];
            #pragma unroll
            for (int mi = 0; mi < 2; mi++) {
                uint32_t base = aRowOff + (uint32_t)mi * 16 * AROW
                    + ((uint32_t)((cbase + aHalf) ^ aRx) << 4);
                ldmatrix_x4(ah[mi][0], ah[mi][1], ah[mi][2], ah[mi][3], base);
                ldmatrix_x4(al[mi][0], al[mi][1], al[mi][2], al[mi][3],
                            base + 128);
            }
            uint32_t b[8][2];
            #pragma unroll
            for (int p = 0; p < 4; p++) {
                int brow = bRowBase + p * 16;
                uint32_t addr = sb + SM_B + (uint32_t)brow * BROW
                    + ((uint32_t)((cbase + bHalf) ^ (brow & 7)) << 4);
                ldmatrix_x4(b[2*p][0], b[2*p][1], b[2*p+1][0], b[2*p+1][1],
                            addr);
            }
            #pragma unroll
            for (int mi = 0; mi < 2; mi++)
                #pragma unroll
                for (int ni = 0; ni < 8; ni++)
                    mma_f16(acc[mi][ni], ah[mi], b[ni][0], b[ni][1]);
            #pragma unroll
            for (int mi = 0; mi < 2; mi++)
                #pragma unroll
                for (int ni = 0; ni < 8; ni++)
                    mma_f16(acc[mi][ni], al[mi], b[ni][0], b[ni][1]);
        }

        // ---- prefetch next tile (LDG hidden under epilogue)
        int tn = t + gridDim.x;
        if (tn < n_tiles) load_tile(f, src, tn, M_total, tid);

        // ---- epilogue: float4 fragments at logical cols nwarp*64+16p+4q
        const int colF4 = nwarp * 16 + q;
        #pragma unroll
        for (int mi = 0; mi < 2; mi++) {
            int r0 = mwarp * 32 + mi * 16 + (lane >> 2);
            int r1 = r0 + 8;
            if (PHASE == 1) {
                const float4* xp0 = (const float4*)
                    (g_xW + (size_t)idx_s[r0] * 128) + colF4;
                const float4* xp1 = (const float4*)
                    (g_xW + (size_t)idx_s[r1] * 128) + colF4;
                float4 g0[4], g1[4];
                #pragma unroll
                for (int p = 0; p < 4; p++) { g0[p] = __ldg(xp0 + p * 4);
                                              g1[p] = __ldg(xp1 + p * 4); }
                int rg0 = t * M_TILE + r0, rg1 = t * M_TILE + r1;
                float4* op0 = (float4*)out + (size_t)rg0 * 32 + colF4;
                float4* op1 = (float4*)out + (size_t)rg1 * 32 + colF4;
                #pragma unroll
                for (int p = 0; p < 4; p++) {
                    float4 o;
                    o.x = fmaxf(acc[mi][2*p][0]   + g0[p].x, 0.0f);
                    o.y = fmaxf(acc[mi][2*p][1]   + g0[p].y, 0.0f);
                    o.z = fmaxf(acc[mi][2*p+1][0] + g0[p].z, 0.0f);
                    o.w = fmaxf(acc[mi][2*p+1][1] + g0[p].w, 0.0f);
                    if (rg0 < M_total) op0[p * 4] = o;
                    o.x = fmaxf(acc[mi][2*p][2]   + g1[p].x, 0.0f);
                    o.y = fmaxf(acc[mi][2*p][3]   + g1[p].y, 0.0f);
                    o.z = fmaxf(acc[mi][2*p+1][2] + g1[p].z, 0.0f);
                    o.w = fmaxf(acc[mi][2*p+1][3] + g1[p].w, 0.0f);
                    if (rg1 < M_total) op1[p * 4] = o;
                }
            } else {
                int rg0 = t * M_TILE + r0, rg1 = t * M_TILE + r1;
                float4* op0 = (float4*)g_xW + (size_t)rg0 * 32 + colF4;
                float4* op1 = (float4*)g_xW + (size_t)rg1 * 32 + colF4;
                #pragma unroll
                for (int p = 0; p < 4; p++) {
                    float4 o;
                    o.x = acc[mi][2*p][0]   + bias4[p].x;
                    o.y = acc[mi][2*p][1]   + bias4[p].y;
                    o.z = acc[mi][2*p+1][0] + bias4[p].z;
                    o.w = acc[mi][2*p+1][1] + bias4[p].w;
                    if (rg0 < M_total) op0[p * 4] = o;
                    o.x = acc[mi][2*p][2]   + bias4[p].x;
                    o.y = acc[mi][2*p][3]   + bias4[p].y;
                    o.z = acc[mi][2*p+1][2] + bias4[p].z;
                    o.w = acc[mi][2*p+1][3] + bias4[p].w;
                    if (rg1 < M_total) op1[p * 4] = o;
                }
            }
        }
        __syncthreads();   // all reads of A done before next conversion
    }
}

// ---------------------------------------------------------------------------
extern "C" void kernel_launch(void* const* d_in, const int* in_sizes, int n_in,
                              void* d_out, int out_size) {
    const float* x         = (const float*)d_in[0];
    const float* edge_attr = (const float*)d_in[1];
    const void*  eidx      = d_in[2];
    const float* W         = (const float*)d_in[3];
    const float* bias      = (const float*)d_in[4];
    float* out             = (float*)d_out;

    const int Nn = in_sizes[0] / 64;
    const int E  = in_sizes[1] / 64;
    const int tiles0 = (Nn + M_TILE - 1) / M_TILE;
    const int tiles1 = (E  + M_TILE - 1) / M_TILE;

    cudaFuncSetAttribute(gemm_kernel<0>,
                         cudaFuncAttributeMaxDynamicSharedMemorySize, SM_TOTAL);
    cudaFuncSetAttribute(gemm_kernel<1>,
                         cudaFuncAttributeMaxDynamicSharedMemorySize, SM_TOTAL);

    // phase 0: smem 83KB -> 2 CTAs/SM; one wave for all node tiles
    int grid0 = tiles0 < 304 ? tiles0 : 304;
    gemm_kernel<0><<<grid0, NT, SM_TOTAL>>>(nullptr, x, eidx, W, bias,
                                            Nn, tiles0);
    int grid1 = tiles1 < 152 ? tiles1 : 152;
    gemm_kernel<1><<<grid1, NT, SM_TOTAL>>>(out, edge_attr, eidx, W, bias,
                                            E, tiles1);
}

// round 14
// speedup vs baseline: 1.4080x; 1.1499x over previous
#include <cuda_runtime.h>
#include <cuda_fp16.h>
#include <cstdint>

// ============================================================================
// DirectedEdgeEncoder on sm_103 (non-'a' target: mma.sync/ldmatrix only).
//
//   out[e] = relu( xW[row[e]] + edge_attr[e] @ W2^T )
//   xW[n]  = x[n] @ W1^T + b          (phase 0, per node)
//
// GEMMs via m16n8k16 fp16:
//   PHASE 0 (nodes, 2-term):  A=[a_hi|a_lo], B=b_hi  -> err ~2e-4 on xW half
//   PHASE 1 (edges, 1-term):  A=a_hi,        B=b_hi  -> err ~3e-4 combined
// Error budget: gate 1e-3; calibrated model predicts ~2.9e-4 total.
//
// Round-10: R9 skeleton unchanged; phase-1 single-term halves MMA count,
// halves A conversion STS, cuts A ldmatrix in half.
// ============================================================================

#define M_TILE   256
#define NT       512
#define BROW     128           // B smem row: 64 fp16 (hi only)

// smem layout (bytes); A sized for the larger (2-term) case
#define SM_B     0                     // 128 x 128 = 16384
#define SM_A     16384                 // up to 256 x 256 = 65536
#define SM_IDX   (16384 + 65536)       // 256 int = 1024
#define SM_FLAG  (SM_IDX + 1024)
#define SM_TOTAL (SM_FLAG + 16)        // 82960

__device__ float g_xW[50432 * 128];    // node @ W1^T + b   (25.8 MB)

// ---------------------------------------------------------------------------
__device__ __forceinline__ uint32_t smem_u32(const void* p) {
    uint32_t a;
    asm("{ .reg .u64 t; cvta.to.shared.u64 t, %1; cvt.u32.u64 %0, t; }"
        : "=r"(a) : "l"(p));
    return a;
}

__device__ __forceinline__ void ldmatrix_x4(uint32_t& r0, uint32_t& r1,
                                            uint32_t& r2, uint32_t& r3,
                                            uint32_t addr) {
    asm volatile("ldmatrix.sync.aligned.m8n8.x4.shared.b16 {%0,%1,%2,%3}, [%4];"
                 : "=r"(r0), "=r"(r1), "=r"(r2), "=r"(r3) : "r"(addr));
}

__device__ __forceinline__ void mma_f16(float* c, const uint32_t* a,
                                        uint32_t b0, uint32_t b1) {
    asm volatile(
        "mma.sync.aligned.m16n8k16.row.col.f32.f16.f16.f32 "
        "{%0,%1,%2,%3}, {%4,%5,%6,%7}, {%8,%9}, {%0,%1,%2,%3};"
        : "+f"(c[0]), "+f"(c[1]), "+f"(c[2]), "+f"(c[3])
        : "r"(a[0]), "r"(a[1]), "r"(a[2]), "r"(a[3]), "r"(b0), "r"(b1));
}

// float4 -> hi (4 fp16) and lo (4 fp16 residuals)
__device__ __forceinline__ void split4h(float4 v, uint2& hi, uint2& lo) {
    __half2 h0 = __floats2half2_rn(v.x, v.y);
    __half2 h1 = __floats2half2_rn(v.z, v.w);
    float2 f0 = __half22float2(h0);
    float2 f1 = __half22float2(h1);
    __half2 l0 = __floats2half2_rn(v.x - f0.x, v.y - f0.y);
    __half2 l1 = __floats2half2_rn(v.z - f1.x, v.w - f1.y);
    hi.x = *reinterpret_cast<uint32_t*>(&h0);
    hi.y = *reinterpret_cast<uint32_t*>(&h1);
    lo.x = *reinterpret_cast<uint32_t*>(&l0);
    lo.y = *reinterpret_cast<uint32_t*>(&l1);
}

__device__ __forceinline__ uint2 pack4h(float4 v) {
    __half2 h0 = __floats2half2_rn(v.x, v.y);
    __half2 h1 = __floats2half2_rn(v.z, v.w);
    uint2 hi;
    hi.x = *reinterpret_cast<uint32_t*>(&h0);
    hi.y = *reinterpret_cast<uint32_t*>(&h1);
    return hi;
}

// swizzled 8B store into a tile with row stride `stride`, 128B block blk
__device__ __forceinline__ void sw_store8(char* base, int r, int blk, int j,
                                          uint2 v, int stride) {
    uint32_t off = (uint32_t)r * stride + (uint32_t)blk * 128
                 + ((uint32_t)(((j >> 1) ^ (r & 7))) << 4) + ((j & 1) << 3);
    *(uint2*)(base + off) = v;
}

__device__ __forceinline__ void load_tile(float4* f, const float* __restrict__ src,
                                          int t, int M_total, int tid) {
    #pragma unroll
    for (int i = 0; i < 8; i++) {
        int idx = i * NT + tid;              // 0..4095
        int r = idx >> 4, j = idx & 15;
        int gr = t * M_TILE + r;
        if (gr >= M_total) gr = 0;           // clamp; stores guarded later
        f[i] = __ldg((const float4*)(src + (size_t)gr * 64 + j * 4));
    }
}

// ---------------------------------------------------------------------------
// PHASE 0 (TERMS=2): g_xW[r] = x[r] @ W[:, :64]^T + bias
// PHASE 1 (TERMS=1): out[e]  = relu( edge_attr[e] @ W[:, 64:]^T + g_xW[row[e]] )
// ---------------------------------------------------------------------------
template <int PHASE>
__global__ void __launch_bounds__(NT, 1)
gemm_kernel(float* __restrict__ out,
            const float* __restrict__ src,        // x or edge_attr [M,64]
            const void*  __restrict__ eidx,
            const float* __restrict__ W,          // [128,128]
            const float* __restrict__ bias,
            int M_total, int n_tiles) {
    constexpr int TERMS = (PHASE == 0) ? 2 : 1;
    constexpr int AROW  = TERMS * 128;       // A smem row bytes

    extern __shared__ char smem[];
    const int tid  = threadIdx.x;
    const int wid  = tid >> 5;
    const int lane = tid & 31;
    const uint32_t sb = smem_u32(smem);

    // ---- dtype sniff for edge_index (int64 LE: odd 32-bit words all zero)
    if (PHASE == 1 && tid < 32) {
        unsigned v = 0;
        #pragma unroll
        for (int s = 0; s < 4; s++)
            v |= ((const unsigned*)eidx)[1 + 2 * (tid * 4 + s)];
        unsigned any = __ballot_sync(0xffffffffu, v != 0u);
        if (tid == 0) *(int*)(smem + SM_FLAG) = (any == 0u) ? 1 : 0;
    }

    // ---- build column-permuted B tile: fp16 hi only, 128B rows
    {
        const float* Wp = W + (PHASE == 0 ? 0 : 64);
        #pragma unroll
        for (int i = 0; i < 4; i++) {
            int idx = i * NT + tid;              // 0..2047
            int ns = idx >> 4;                   // B smem row 0..127
            int j  = idx & 15;
            int nw   = ns >> 6;
            int rest = ns & 63;
            int ni = rest >> 3, pos = rest & 7;
            int q = pos >> 1, jj = pos & 1;
            int L = nw * 64 + ((ni >> 1) << 4) + (q << 2) + ((ni & 1) << 1) + jj;
            float4 v = *(const float4*)(Wp + L * 128 + j * 4);
            sw_store8(smem + SM_B, ns, 0, j, pack4h(v), BROW);
        }
    }

    // ---- prologue: load first tile into registers
    float4 f[8];
    if (blockIdx.x < n_tiles) load_tile(f, src, blockIdx.x, M_total, tid);
    __syncthreads();

    const int is64 = (PHASE == 1) ? *(const int*)(smem + SM_FLAG) : 0;

    const int mwarp = wid >> 1;              // 0..7  (32 rows each)
    const int nwarp = wid & 1;               // 0..1  (64 cols each)
    const int q     = lane & 3;

    const int aRow = mwarp * 32 + (lane & 7) + (((lane >> 3) & 1) << 3);
    const uint32_t aRowOff = sb + SM_A + (uint32_t)aRow * AROW;
    const int aRx = aRow & 7;
    const int aHalf = lane >> 4;
    const int bRowBase = nwarp * 64 + ((lane >> 4) << 3) + (lane & 7);
    const int bHalf = (lane >> 3) & 1;

    float4 bias4[4];
    if (PHASE == 0) {
        #pragma unroll
        for (int p = 0; p < 4; p++)
            bias4[p] = ((const float4*)bias)[nwarp * 16 + p * 4 + q];
    }

    int* idx_s = (int*)(smem + SM_IDX);

    for (int t = blockIdx.x; t < n_tiles; t += gridDim.x) {
        // ---- convert regs -> A tile: fp16 hi (+ lo if TERMS==2)
        {
            const int j = tid & 15;
            #pragma unroll
            for (int i = 0; i < 8; i++) {
                int r = i * 32 + (tid >> 4);
                if (TERMS == 2) {
                    uint2 hi, lo;
                    split4h(f[i], hi, lo);
                    sw_store8(smem + SM_A, r, 0, j, hi, AROW);
                    sw_store8(smem + SM_A, r, 1, j, lo, AROW);
                } else {
                    sw_store8(smem + SM_A, r, 0, j, pack4h(f[i]), AROW);
                }
            }
        }
        if (PHASE == 1 && tid < M_TILE) {
            int e = t * M_TILE + tid;
            int r = 0;
            if (e < M_total)
                r = is64 ? (int)((const long long*)eidx)[e]
                         : ((const int*)eidx)[e];
            idx_s[tid] = r;
        }
        __syncthreads();

        // ---- MMA: warp tile M32 x N64
        float acc[2][8][4];
        #pragma unroll
        for (int mi = 0; mi < 2; mi++)
            #pragma unroll
            for (int ni = 0; ni < 8; ni++)
                #pragma unroll
                for (int c = 0; c < 4; c++) acc[mi][ni][c] = 0.0f;

        #pragma unroll
        for (int cc = 0; cc < 4; cc++) {
            const int cbase = cc * 2;
            uint32_t ah[2][4], al[2][4];
            #pragma unroll
            for (int mi = 0; mi < 2; mi++) {
                uint32_t base = aRowOff + (uint32_t)mi * 16 * AROW
                    + ((uint32_t)((cbase + aHalf) ^ aRx) << 4);
                ldmatrix_x4(ah[mi][0], ah[mi][1], ah[mi][2], ah[mi][3], base);
                if (TERMS == 2)
                    ldmatrix_x4(al[mi][0], al[mi][1], al[mi][2], al[mi][3],
                                base + 128);
            }
            uint32_t b[8][2];
            #pragma unroll
            for (int p = 0; p < 4; p++) {
                int brow = bRowBase + p * 16;
                uint32_t addr = sb + SM_B + (uint32_t)brow * BROW
                    + ((uint32_t)((cbase + bHalf) ^ (brow & 7)) << 4);
                ldmatrix_x4(b[2*p][0], b[2*p][1], b[2*p+1][0], b[2*p+1][1],
                            addr);
            }
            #pragma unroll
            for (int mi = 0; mi < 2; mi++)
                #pragma unroll
                for (int ni = 0; ni < 8; ni++)
                    mma_f16(acc[mi][ni], ah[mi], b[ni][0], b[ni][1]);
            if (TERMS == 2) {
                #pragma unroll
                for (int mi = 0; mi < 2; mi++)
                    #pragma unroll
                    for (int ni = 0; ni < 8; ni++)
                        mma_f16(acc[mi][ni], al[mi], b[ni][0], b[ni][1]);
            }
        }

        // ---- prefetch next tile (LDG hidden under epilogue)
        int tn = t + gridDim.x;
        if (tn < n_tiles) load_tile(f, src, tn, M_total, tid);

        // ---- epilogue: float4 fragments at logical cols nwarp*64+16p+4q
        const int colF4 = nwarp * 16 + q;
        #pragma unroll
        for (int mi = 0; mi < 2; mi++) {
            int r0 = mwarp * 32 + mi * 16 + (lane >> 2);
            int r1 = r0 + 8;
            if (PHASE == 1) {
                const float4* xp0 = (const float4*)
                    (g_xW + (size_t)idx_s[r0] * 128) + colF4;
                const float4* xp1 = (const float4*)
                    (g_xW + (size_t)idx_s[r1] * 128) + colF4;
                float4 g0[4], g1[4];
                #pragma unroll
                for (int p = 0; p < 4; p++) { g0[p] = __ldg(xp0 + p * 4);
                                              g1[p] = __ldg(xp1 + p * 4); }
                int rg0 = t * M_TILE + r0, rg1 = t * M_TILE + r1;
                float4* op0 = (float4*)out + (size_t)rg0 * 32 + colF4;
                float4* op1 = (float4*)out + (size_t)rg1 * 32 + colF4;
                #pragma unroll
                for (int p = 0; p < 4; p++) {
                    float4 o;
                    o.x = fmaxf(acc[mi][2*p][0]   + g0[p].x, 0.0f);
                    o.y = fmaxf(acc[mi][2*p][1]   + g0[p].y, 0.0f);
                    o.z = fmaxf(acc[mi][2*p+1][0] + g0[p].z, 0.0f);
                    o.w = fmaxf(acc[mi][2*p+1][1] + g0[p].w, 0.0f);
                    if (rg0 < M_total) op0[p * 4] = o;
                    o.x = fmaxf(acc[mi][2*p][2]   + g1[p].x, 0.0f);
                    o.y = fmaxf(acc[mi][2*p][3]   + g1[p].y, 0.0f);
                    o.z = fmaxf(acc[mi][2*p+1][2] + g1[p].z, 0.0f);
                    o.w = fmaxf(acc[mi][2*p+1][3] + g1[p].w, 0.0f);
                    if (rg1 < M_total) op1[p * 4] = o;
                }
            } else {
                int rg0 = t * M_TILE + r0, rg1 = t * M_TILE + r1;
                float4* op0 = (float4*)g_xW + (size_t)rg0 * 32 + colF4;
                float4* op1 = (float4*)g_xW + (size_t)rg1 * 32 + colF4;
                #pragma unroll
                for (int p = 0; p < 4; p++) {
                    float4 o;
                    o.x = acc[mi][2*p][0]   + bias4[p].x;
                    o.y = acc[mi][2*p][1]   + bias4[p].y;
                    o.z = acc[mi][2*p+1][0] + bias4[p].z;
                    o.w = acc[mi][2*p+1][1] + bias4[p].w;
                    if (rg0 < M_total) op0[p * 4] = o;
                    o.x = acc[mi][2*p][2]   + bias4[p].x;
                    o.y = acc[mi][2*p][3]   + bias4[p].y;
                    o.z = acc[mi][2*p+1][2] + bias4[p].z;
                    o.w = acc[mi][2*p+1][3] + bias4[p].w;
                    if (rg1 < M_total) op1[p * 4] = o;
                }
            }
        }
        __syncthreads();   // all reads of A done before next conversion
    }
}

// ---------------------------------------------------------------------------
extern "C" void kernel_launch(void* const* d_in, const int* in_sizes, int n_in,
                              void* d_out, int out_size) {
    const float* x         = (const float*)d_in[0];
    const float* edge_attr = (const float*)d_in[1];
    const void*  eidx      = d_in[2];
    const float* W         = (const float*)d_in[3];
    const float* bias      = (const float*)d_in[4];
    float* out             = (float*)d_out;

    const int Nn = in_sizes[0] / 64;
    const int E  = in_sizes[1] / 64;
    const int tiles0 = (Nn + M_TILE - 1) / M_TILE;
    const int tiles1 = (E  + M_TILE - 1) / M_TILE;

    cudaFuncSetAttribute(gemm_kernel<0>,
                         cudaFuncAttributeMaxDynamicSharedMemorySize, SM_TOTAL);
    cudaFuncSetAttribute(gemm_kernel<1>,
                         cudaFuncAttributeMaxDynamicSharedMemorySize, SM_TOTAL);

    int grid0 = tiles0 < 152 ? tiles0 : 152;
    gemm_kernel<0><<<grid0, NT, SM_TOTAL>>>(nullptr, x, eidx, W, bias,
                                            Nn, tiles0);
    int grid1 = tiles1 < 152 ? tiles1 : 152;
    gemm_kernel<1><<<grid1, NT, SM_TOTAL>>>(out, edge_attr, eidx, W, bias,
                                            E, tiles1);
}